// round 2
// baseline (speedup 1.0000x reference)
#include <cuda_runtime.h>
#include <cstdint>
#include <cstddef>

#define DIMK     256
#define NBATCH   16
#define TILE_M   64
#define NTHREADS 256
#define KC       16
#define NKC      (DIMK / KC)
#define SMEM_BYTES ((TILE_M * DIMK + 2 * KC * DIMK) * 4)

typedef unsigned long long u64;

// u_proj[b,d] + b1[d], produced by prep kernel, consumed by main kernel
__device__ float g_up[NBATCH * DIMK];

// ---------------- packed f32x2 helpers (Blackwell) ----------------
__device__ __forceinline__ u64 pack_dup(float x) {
    u64 r; asm("mov.b64 %0, {%1, %1};" : "=l"(r) : "f"(x)); return r;
}
__device__ __forceinline__ void unpack2(u64 v, float& lo, float& hi) {
    asm("mov.b64 {%0, %1}, %2;" : "=f"(lo), "=f"(hi) : "l"(v));
}
__device__ __forceinline__ void ffma2(u64& d, u64 a, u64 b) {
    asm("fma.rn.f32x2 %0, %1, %2, %0;" : "+l"(d) : "l"(a), "l"(b));
}
__device__ __forceinline__ u64 lds_b64(uint32_t addr) {
    u64 r; asm volatile("ld.shared.b64 %0, [%1];" : "=l"(r) : "r"(addr)); return r;
}
__device__ __forceinline__ void cp_async16(uint32_t dst, const void* src) {
    asm volatile("cp.async.cg.shared.global [%0], [%1], 16;" :: "r"(dst), "l"(src));
}

// ---------------- prep: up[b][d] = u[b] @ Wu + b1 ----------------
// grid (4, 16), 256 threads. 4 threads cooperate per output d (64 k each).
__global__ void prep_kernel(const int* __restrict__ inst,
                            const float* __restrict__ user_table,
                            const float* __restrict__ W1,
                            const float* __restrict__ b1) {
    __shared__ float u[DIMK];
    int b = blockIdx.y;
    int tid = threadIdx.x;

    // instances may be int32 (jax default) or int64. For int64, every odd
    // int32 word is a zero high-half (values < 100000). For int32 those words
    // are random indices; all-zero is ~impossible.
    bool w64 = true;
#pragma unroll
    for (int i = 1; i < 16; i += 2) w64 = w64 && (inst[i] == 0);
    int row = w64 ? inst[2 * b] : inst[b];

    if (tid < 64)
        ((float4*)u)[tid] = ((const float4*)(user_table + (size_t)row * DIMK))[tid];
    __syncthreads();

    int d  = blockIdx.x * 64 + (tid >> 2);
    int ks = (tid & 3) * 64;
    float acc = 0.f;
#pragma unroll 8
    for (int k = 0; k < 64; k++)
        acc = fmaf(u[ks + k], W1[(size_t)(ks + k) * DIMK + d], acc);
    acc += __shfl_xor_sync(0xffffffffu, acc, 1);
    acc += __shfl_xor_sync(0xffffffffu, acc, 2);
    if ((tid & 3) == 0) g_up[b * DIMK + d] = acc + b1[d];
}

// ---------------- main: fused i_proj GEMM + relu-dot epilogue ----------------
__global__ void __launch_bounds__(NTHREADS, 2)
main_kernel(const float* __restrict__ item,
            const float* __restrict__ W1,
            const float* __restrict__ W2v,
            const float* __restrict__ b2,
            float* __restrict__ out, int M) {
    extern __shared__ float smem[];
    float* As = smem;  // TILE_M x DIMK item tile (fp32), later reused for C
    uint32_t smem_u32 = (uint32_t)__cvta_generic_to_shared(smem);
    uint32_t ws_u32   = smem_u32 + TILE_M * DIMK * 4;  // 2 x KC x DIMK Wi bufs

    int tid = threadIdx.x;
    int tx = tid & 31, ty = tid >> 5;
    int m0 = blockIdx.x * TILE_M;

    // Load A tile (zero-pad tail rows)
    {
        int valid_rows = M - m0; if (valid_rows > TILE_M) valid_rows = TILE_M;
        const float4* src = (const float4*)(item + (size_t)m0 * DIMK);
        float4* dst = (float4*)As;
#pragma unroll
        for (int j = 0; j < TILE_M * DIMK / 4 / NTHREADS; j++) {
            int idx = tid + j * NTHREADS;
            int r = idx >> 6;  // 64 float4 per row
            float4 v = make_float4(0.f, 0.f, 0.f, 0.f);
            if (r < valid_rows) v = src[idx];
            dst[idx] = v;
        }
    }

    const float* Wi = W1 + DIMK * DIMK;  // W1 rows 256..511

    // Prefetch Wi chunk 0 into buffer 0
#pragma unroll
    for (int j = 0; j < 4; j++)
        cp_async16(ws_u32 + (uint32_t)(tid + j * NTHREADS) * 16,
                   (const float4*)Wi + tid + j * NTHREADS);
    asm volatile("cp.async.commit_group;");

    // 8 rows x 8 cols per thread, packed as 4 col-pairs:
    // p0=(tx*4,tx*4+1) p1=(tx*4+2,tx*4+3) p2/p3 = same +128.
    u64 acc[8][4];
#pragma unroll
    for (int i = 0; i < 8; i++)
#pragma unroll
        for (int p = 0; p < 4; p++) acc[i][p] = 0ull;

    for (int c = 0; c < NKC; c++) {
        if (c + 1 < NKC) {
            const float4* src = (const float4*)(Wi + (size_t)(c + 1) * KC * DIMK);
            uint32_t dbuf = ws_u32 + (uint32_t)((c + 1) & 1) * (KC * DIMK * 4);
#pragma unroll
            for (int j = 0; j < 4; j++)
                cp_async16(dbuf + (uint32_t)(tid + j * NTHREADS) * 16,
                           src + tid + j * NTHREADS);
            asm volatile("cp.async.commit_group;");
            asm volatile("cp.async.wait_group 1;");
        } else {
            asm volatile("cp.async.wait_group 0;");
        }
        __syncthreads();

        uint32_t bbuf = ws_u32 + (uint32_t)(c & 1) * (KC * DIMK * 4);
        int k0 = c * KC;
#pragma unroll
        for (int kk = 0; kk < KC; kk += 2) {
            int k = k0 + kk;
            // broadcast-load a-pairs (k, k+1) for this thread's 8 rows
            u64 ap[8];
#pragma unroll
            for (int i = 0; i < 8; i++)
                ap[i] = lds_b64(smem_u32 + (uint32_t)(((ty * 8 + i) * DIMK + k) * 4));
#pragma unroll
            for (int s = 0; s < 2; s++) {
                uint32_t rowb = bbuf + (uint32_t)((kk + s) * DIMK * 4);
                u64 b0  = lds_b64(rowb + (uint32_t)(tx * 16));
                u64 b1p = lds_b64(rowb + (uint32_t)(tx * 16 + 8));
                u64 b2p = lds_b64(rowb + (uint32_t)(512 + tx * 16));
                u64 b3p = lds_b64(rowb + (uint32_t)(512 + tx * 16 + 8));
#pragma unroll
                for (int i = 0; i < 8; i++) {
                    float alo, ahi; unpack2(ap[i], alo, ahi);
                    u64 a2 = pack_dup(s == 0 ? alo : ahi);
                    ffma2(acc[i][0], a2, b0);
                    ffma2(acc[i][1], a2, b1p);
                    ffma2(acc[i][2], a2, b2p);
                    ffma2(acc[i][3], a2, b3p);
                }
            }
        }
        __syncthreads();  // protect buffer (c&1) from the prefetch at iter c+1
    }

    // ---------------- epilogue ----------------
    // Spill C into the A-tile smem (A no longer needed).
    {
#pragma unroll
        for (int i = 0; i < 8; i++) {
            float2* dst = (float2*)&As[(ty * 8 + i) * DIMK];
            float lo, hi;
            unpack2(acc[i][0], lo, hi); dst[tx * 2]          = make_float2(lo, hi);
            unpack2(acc[i][1], lo, hi); dst[tx * 2 + 1]      = make_float2(lo, hi);
            unpack2(acc[i][2], lo, hi); dst[64 + tx * 2]     = make_float2(lo, hi);
            unpack2(acc[i][3], lo, hi); dst[64 + tx * 2 + 1] = make_float2(lo, hi);
        }
    }
    // Load up (16x256) and w2 (256) into the Wi-buffer smem region.
    float* ups = smem + TILE_M * DIMK;
    float* w2s = ups + NBATCH * DIMK;
    for (int i = tid; i < NBATCH * DIMK; i += NTHREADS) ups[i] = g_up[i];
    for (int i = tid; i < DIMK; i += NTHREADS) w2s[i] = W2v[i];
    __syncthreads();

    // Each warp owns its 8 rows; lane covers cols lane*4..+3 and 128+lane*4..+3.
    float4 w0 = ((const float4*)w2s)[tx];
    float4 w1 = ((const float4*)w2s)[32 + tx];
    float b2v = b2[0];

    for (int b = 0; b < NBATCH; b++) {
        const float4* ub = (const float4*)(ups + b * DIMK);
        float4 u0 = ub[tx];
        float4 u1 = ub[32 + tx];
#pragma unroll
        for (int i = 0; i < 8; i++) {
            int row = ty * 8 + i;
            const float4* crow = (const float4*)&As[row * DIMK];
            float4 c0 = crow[tx];
            float4 c1 = crow[32 + tx];
            float s;
            s = fmaxf(c0.x + u0.x, 0.f) * w0.x;
            s = fmaf(fmaxf(c0.y + u0.y, 0.f), w0.y, s);
            s = fmaf(fmaxf(c0.z + u0.z, 0.f), w0.z, s);
            s = fmaf(fmaxf(c0.w + u0.w, 0.f), w0.w, s);
            s = fmaf(fmaxf(c1.x + u1.x, 0.f), w1.x, s);
            s = fmaf(fmaxf(c1.y + u1.y, 0.f), w1.y, s);
            s = fmaf(fmaxf(c1.z + u1.z, 0.f), w1.z, s);
            s = fmaf(fmaxf(c1.w + u1.w, 0.f), w1.w, s);
            s += __shfl_xor_sync(0xffffffffu, s, 16);
            s += __shfl_xor_sync(0xffffffffu, s, 8);
            s += __shfl_xor_sync(0xffffffffu, s, 4);
            s += __shfl_xor_sync(0xffffffffu, s, 2);
            s += __shfl_xor_sync(0xffffffffu, s, 1);
            int m = m0 + row;
            if (tx == 0 && m < M) out[b * M + m] = s + b2v;
        }
    }
}

extern "C" void kernel_launch(void* const* d_in, const int* in_sizes, int n_in,
                              void* d_out, int out_size) {
    const int*   inst       = (const int*)d_in[0];
    const float* user_table = (const float*)d_in[1];
    const float* item       = (const float*)d_in[2];
    const float* W1         = (const float*)d_in[3];
    const float* b1         = (const float*)d_in[4];
    const float* W2v        = (const float*)d_in[5];
    const float* b2         = (const float*)d_in[6];
    float* out = (float*)d_out;
    int M = in_sizes[2] / DIMK;  // item_table rows

    cudaFuncSetAttribute(main_kernel,
                         cudaFuncAttributeMaxDynamicSharedMemorySize, SMEM_BYTES);

    prep_kernel<<<dim3(4, 16), 256>>>(inst, user_table, W1, b1);
    main_kernel<<<(M + TILE_M - 1) / TILE_M, NTHREADS, SMEM_BYTES>>>(
        item, W1, W2v, b2, out, M);
}

// round 4
// speedup vs baseline: 1.7757x; 1.7757x over previous
#include <cuda_runtime.h>
#include <cuda_bf16.h>
#include <cstdint>
#include <cstddef>

#define DIMK     256
#define NBATCH   16
#define TILE_M   128

typedef unsigned long long u64;

// ---------------- device globals ----------------
__device__ float g_up[NBATCH * DIMK];                 // u@Wu + b1
__device__ __nv_bfloat16 g_Bhi[DIMK * DIMK];          // B[n][k] = Wi[k][n], hi part
__device__ __nv_bfloat16 g_Blo[DIMK * DIMK];          // lo part

// ---------------- smem layout (main) ----------------
#define SM_AH  0                    // 128 rows x 128B  (128x64 bf16 hi)
#define SM_AL  (16 * 1024)
#define SM_BH  (32 * 1024)          // 256 rows x 128B  (256x64 bf16 hi)
#define SM_BL  (64 * 1024)
#define SM_UP  (96 * 1024)          // 16 x 256 fp32
#define SM_W2  (112 * 1024)         // 256 fp32
#define SMEM_TOTAL (113 * 1024)

// ---------------- helpers ----------------
__device__ __forceinline__ u64 pack2f(float lo, float hi) {
    u64 r; asm("mov.b64 %0, {%1, %2};" : "=l"(r) : "f"(lo), "f"(hi)); return r;
}
__device__ __forceinline__ void unpack2(u64 v, float& lo, float& hi) {
    asm("mov.b64 {%0, %1}, %2;" : "=f"(lo), "=f"(hi) : "l"(v));
}
__device__ __forceinline__ u64 add2(u64 a, u64 b) {
    u64 r; asm("add.rn.f32x2 %0, %1, %2;" : "=l"(r) : "l"(a), "l"(b)); return r;
}
__device__ __forceinline__ void ffma2(u64& d, u64 a, u64 b) {
    asm("fma.rn.f32x2 %0, %1, %2, %0;" : "+l"(d) : "l"(a), "l"(b));
}
__device__ __forceinline__ u64 relu2(u64 x) {
    u64 r;
    asm("{\n\t.reg .f32 lo, hi;\n\t"
        "mov.b64 {lo, hi}, %1;\n\t"
        "max.f32 lo, lo, 0f00000000;\n\t"
        "max.f32 hi, hi, 0f00000000;\n\t"
        "mov.b64 %0, {lo, hi};\n\t}" : "=l"(r) : "l"(x));
    return r;
}
__device__ __forceinline__ u64 lds_b64(uint32_t addr) {
    u64 r; asm volatile("ld.shared.b64 %0, [%1];" : "=l"(r) : "r"(addr)); return r;
}
__device__ __forceinline__ void cp_async16(uint32_t dst, const void* src) {
    asm volatile("cp.async.cg.shared.global [%0], [%1], 16;" :: "r"(dst), "l"(src));
}
__device__ __forceinline__ void ldsm4(uint32_t* r, uint32_t addr) {
    asm volatile("ldmatrix.sync.aligned.m8n8.x4.shared.b16 {%0,%1,%2,%3}, [%4];"
        : "=r"(r[0]), "=r"(r[1]), "=r"(r[2]), "=r"(r[3]) : "r"(addr));
}
__device__ __forceinline__ void mma16816(float* c, const uint32_t* a,
                                         uint32_t b0, uint32_t b1) {
    asm volatile("mma.sync.aligned.m16n8k16.row.col.f32.bf16.bf16.f32 "
        "{%0,%1,%2,%3}, {%4,%5,%6,%7}, {%8,%9}, {%0,%1,%2,%3};"
        : "+f"(c[0]), "+f"(c[1]), "+f"(c[2]), "+f"(c[3])
        : "r"(a[0]), "r"(a[1]), "r"(a[2]), "r"(a[3]), "r"(b0), "r"(b1));
}
// split two fp32 into packed bf16x2 hi and lo words
__device__ __forceinline__ void split2(float x, float y, uint32_t& hp, uint32_t& lp) {
    __nv_bfloat16 h0 = __float2bfloat16(x);
    __nv_bfloat16 h1 = __float2bfloat16(y);
    __nv_bfloat16 l0 = __float2bfloat16(x - __bfloat162float(h0));
    __nv_bfloat16 l1 = __float2bfloat16(y - __bfloat162float(h1));
    __nv_bfloat162 hh; hh.x = h0; hh.y = h1;
    __nv_bfloat162 ll; ll.x = l0; ll.y = l1;
    hp = *reinterpret_cast<uint32_t*>(&hh);
    lp = *reinterpret_cast<uint32_t*>(&ll);
}

// ---------------- prep: up[b][d] = u[b] @ Wu + b1 ----------------
__global__ void prep_kernel(const int* __restrict__ inst,
                            const float* __restrict__ user_table,
                            const float* __restrict__ W1,
                            const float* __restrict__ b1) {
    __shared__ float u[DIMK];
    int b = blockIdx.y;
    int tid = threadIdx.x;
    bool w64 = true;
#pragma unroll
    for (int i = 1; i < 16; i += 2) w64 = w64 && (inst[i] == 0);
    int row = w64 ? inst[2 * b] : inst[b];
    if (tid < 64)
        ((float4*)u)[tid] = ((const float4*)(user_table + (size_t)row * DIMK))[tid];
    __syncthreads();
    int d  = blockIdx.x * 64 + (tid >> 2);
    int ks = (tid & 3) * 64;
    float acc = 0.f;
#pragma unroll 8
    for (int k = 0; k < 64; k++)
        acc = fmaf(u[ks + k], W1[(size_t)(ks + k) * DIMK + d], acc);
    acc += __shfl_xor_sync(0xffffffffu, acc, 1);
    acc += __shfl_xor_sync(0xffffffffu, acc, 2);
    if ((tid & 3) == 0) g_up[b * DIMK + d] = acc + b1[d];
}

// ---------------- convB: B[n][k] = Wi[k][n], fp32 -> bf16 hi/lo ----------------
// grid 8 CTAs x 256 thr; CTA handles 32 n-columns, smem-transposed.
__global__ void convB_kernel(const float* __restrict__ W1) {
    __shared__ float tile[32][33];
    const float* Wi = W1 + DIMK * DIMK;
    int n0 = blockIdx.x * 32;
    int tid = threadIdx.x;
    int tr = tid >> 5, tc = tid & 31;   // tr 0..7
    for (int kb = 0; kb < 8; kb++) {
#pragma unroll
        for (int p = 0; p < 4; p++) {
            int k = kb * 32 + p * 8 + tr;
            tile[p * 8 + tr][tc] = Wi[(size_t)k * DIMK + n0 + tc];
        }
        __syncthreads();
#pragma unroll
        for (int p = 0; p < 4; p++) {
            int nl = p * 8 + tr;
            float x = tile[tc][nl];
            __nv_bfloat16 h = __float2bfloat16(x);
            __nv_bfloat16 l = __float2bfloat16(x - __bfloat162float(h));
            size_t off = (size_t)(n0 + nl) * DIMK + kb * 32 + tc;
            g_Bhi[off] = h;
            g_Blo[off] = l;
        }
        __syncthreads();
    }
}

// ---------------- main: bf16-split mma.sync GEMM + fused epilogue ----------------
__global__ void __launch_bounds__(256, 1)
main_kernel(const float* __restrict__ item,
            const float* __restrict__ W2v, const float* __restrict__ b2,
            float* __restrict__ out, int M) {
    extern __shared__ __align__(1024) char smem[];
    uint32_t sb = (uint32_t)__cvta_generic_to_shared(smem);
    int tid = threadIdx.x, wid = tid >> 5, lane = tid & 31;
    int m0 = blockIdx.x * TILE_M;

    // stage up / w2
    for (int i = tid; i < NBATCH * DIMK; i += 256)
        ((float*)(smem + SM_UP))[i] = g_up[i];
    if (tid < 64)
        ((float4*)(smem + SM_W2))[tid] = ((const float4*)W2v)[tid];

    float acc[32][4];
#pragma unroll
    for (int j = 0; j < 32; j++)
#pragma unroll
        for (int q = 0; q < 4; q++) acc[j][q] = 0.f;

#pragma unroll 1
    for (int c = 0; c < 4; c++) {
        __syncthreads();  // previous chunk's ldmatrix reads done; also covers up/w2 staging

        // B hi/lo chunk via cp.async (swizzled 16B chunks)
#pragma unroll
        for (int i = 0; i < 8; i++) {
            int id = tid + i * 256;
            int n = id >> 3, kc = id & 7;
            uint32_t soff = (uint32_t)n * 128 + (uint32_t)((kc ^ (n & 7)) << 4);
            size_t goff = (size_t)n * 512 + (size_t)c * 128 + (size_t)kc * 16;
            cp_async16(sb + SM_BH + soff, (const char*)g_Bhi + goff);
            cp_async16(sb + SM_BL + soff, (const char*)g_Blo + goff);
        }
        asm volatile("cp.async.commit_group;" ::: "memory");

        // A chunk: LDG fp32 -> split -> swizzled STS
#pragma unroll
        for (int i = 0; i < 4; i++) {
            int id = tid + i * 256;
            int r = id >> 3, kg = id & 7;
            int m = m0 + r;
            float4 v0 = make_float4(0.f, 0.f, 0.f, 0.f), v1 = v0;
            if (m < M) {
                const float4* p = (const float4*)(item + (size_t)m * DIMK + c * 64 + kg * 8);
                v0 = p[0]; v1 = p[1];
            }
            uint32_t h[4], l[4];
            split2(v0.x, v0.y, h[0], l[0]);
            split2(v0.z, v0.w, h[1], l[1]);
            split2(v1.x, v1.y, h[2], l[2]);
            split2(v1.z, v1.w, h[3], l[3]);
            uint32_t off = (uint32_t)r * 128 + (uint32_t)((kg ^ (r & 7)) << 4);
            *(uint4*)(smem + SM_AH + off) = make_uint4(h[0], h[1], h[2], h[3]);
            *(uint4*)(smem + SM_AL + off) = make_uint4(l[0], l[1], l[2], l[3]);
        }
        asm volatile("cp.async.wait_group 0;" ::: "memory");
        __syncthreads();

        // MMA: warp rows 16*wid .. +15, all 256 N
        int mb = wid * 16;
#pragma unroll 1
        for (int ks = 0; ks < 4; ks++) {
            int arow = mb + (lane & 15);
            int akc = 2 * ks + (lane >> 4);
            uint32_t aoff = (uint32_t)arow * 128 + (uint32_t)((akc ^ (arow & 7)) << 4);
            uint32_t ah[4], al[4];
            ldsm4(ah, sb + SM_AH + aoff);
            ldsm4(al, sb + SM_AL + aoff);

            int brow7 = (lane & 7) + ((lane >> 4) & 1) * 8;
            int bkc = 2 * ks + ((lane >> 3) & 1);
#pragma unroll
            for (int j = 0; j < 32; j += 2) {
                int brow = 8 * j + brow7;
                uint32_t boff = (uint32_t)brow * 128 + (uint32_t)((bkc ^ (brow & 7)) << 4);
                uint32_t bh[4], bl[4];
                ldsm4(bh, sb + SM_BH + boff);
                ldsm4(bl, sb + SM_BL + boff);
                mma16816(acc[j],     ah, bh[0], bh[1]);
                mma16816(acc[j],     al, bh[0], bh[1]);
                mma16816(acc[j],     ah, bl[0], bl[1]);
                mma16816(acc[j + 1], ah, bh[2], bh[3]);
                mma16816(acc[j + 1], al, bh[2], bh[3]);
                mma16816(acc[j + 1], ah, bl[2], bl[3]);
            }
        }
    }

    // ---------------- epilogue (register accumulators) ----------------
    int R0 = m0 + wid * 16 + (lane >> 2);
    int R1 = R0 + 8;
    float b2v = b2[0];
    uint32_t ubase = sb + SM_UP + (uint32_t)((lane & 3) * 8);
    uint32_t wbase = sb + SM_W2 + (uint32_t)((lane & 3) * 8);

#pragma unroll 1
    for (int b = 0; b < NBATCH; b++) {
        u64 s0 = 0ull, s1 = 0ull;
        uint32_t ub = ubase + (uint32_t)b * 1024;
#pragma unroll
        for (int j = 0; j < 32; j++) {
            u64 u2 = lds_b64(ub + j * 32);
            u64 w2 = lds_b64(wbase + j * 32);
            u64 p0 = pack2f(acc[j][0], acc[j][1]);
            u64 p1 = pack2f(acc[j][2], acc[j][3]);
            ffma2(s0, relu2(add2(p0, u2)), w2);
            ffma2(s1, relu2(add2(p1, u2)), w2);
        }
        float lo, hi;
        unpack2(s0, lo, hi); float r0 = lo + hi;
        unpack2(s1, lo, hi); float r1 = lo + hi;
        r0 += __shfl_xor_sync(0xffffffffu, r0, 1);
        r0 += __shfl_xor_sync(0xffffffffu, r0, 2);
        r1 += __shfl_xor_sync(0xffffffffu, r1, 1);
        r1 += __shfl_xor_sync(0xffffffffu, r1, 2);
        if ((lane & 3) == 0) {
            if (R0 < M) out[(size_t)b * M + R0] = r0 + b2v;
            if (R1 < M) out[(size_t)b * M + R1] = r1 + b2v;
        }
    }
}

extern "C" void kernel_launch(void* const* d_in, const int* in_sizes, int n_in,
                              void* d_out, int out_size) {
    const int*   inst       = (const int*)d_in[0];
    const float* user_table = (const float*)d_in[1];
    const float* item       = (const float*)d_in[2];
    const float* W1         = (const float*)d_in[3];
    const float* b1         = (const float*)d_in[4];
    const float* W2v        = (const float*)d_in[5];
    const float* b2         = (const float*)d_in[6];
    float* out = (float*)d_out;
    int M = in_sizes[2] / DIMK;
    int ntiles = (M + TILE_M - 1) / TILE_M;

    cudaFuncSetAttribute(main_kernel,
                         cudaFuncAttributeMaxDynamicSharedMemorySize, SMEM_TOTAL);

    prep_kernel<<<dim3(4, 16), 256>>>(inst, user_table, W1, b1);
    convB_kernel<<<8, 256>>>(W1);
    main_kernel<<<ntiles, 256, SMEM_TOTAL>>>(item, W2v, b2, out, M);
}